// round 14
// baseline (speedup 1.0000x reference)
#include <cuda_runtime.h>
#include <stdint.h>

#define N_NODES_MAX 100000
#define D_DIM 128

// Per-node projection table: {h·Wu[0]+b0, h·Wu[1]+b1, h·Wv[0], h·Wv[1]}
__device__ float4 g_p[N_NODES_MAX];

// ---------------------------------------------------------------------------
// Phase 1: one warp per node. Each lane loads one float4 of the 128-wide h row
// (32 lanes * 4 = 128), dots against W slices, warp-reduces 4 sums.
// ---------------------------------------------------------------------------
__global__ void __launch_bounds__(256)
node_proj_kernel(const float* __restrict__ h,
                 const float* __restrict__ W,   // [2, 256] row-major
                 const float* __restrict__ b,
                 int n_nodes)
{
    const int warp_in_block = threadIdx.x >> 5;
    const int lane          = threadIdx.x & 31;
    const int node = blockIdx.x * (blockDim.x >> 5) + warp_in_block;
    if (node >= n_nodes) return;

    const float4 hv = __ldg(((const float4*)(h + (size_t)node * D_DIM)) + lane);

    // W row 0 = [Wu0 (128) | Wv0 (128)], row 1 = [Wu1 | Wv1]
    const float4 wu0 = __ldg(((const float4*)(W      )) + lane);
    const float4 wv0 = __ldg(((const float4*)(W + 128)) + lane);
    const float4 wu1 = __ldg(((const float4*)(W + 256)) + lane);
    const float4 wv1 = __ldg(((const float4*)(W + 384)) + lane);

    float s0 = hv.x*wu0.x + hv.y*wu0.y + hv.z*wu0.z + hv.w*wu0.w;
    float s1 = hv.x*wu1.x + hv.y*wu1.y + hv.z*wu1.z + hv.w*wu1.w;
    float s2 = hv.x*wv0.x + hv.y*wv0.y + hv.z*wv0.z + hv.w*wv0.w;
    float s3 = hv.x*wv1.x + hv.y*wv1.y + hv.z*wv1.z + hv.w*wv1.w;

    #pragma unroll
    for (int off = 16; off > 0; off >>= 1) {
        s0 += __shfl_xor_sync(0xFFFFFFFFu, s0, off);
        s1 += __shfl_xor_sync(0xFFFFFFFFu, s1, off);
        s2 += __shfl_xor_sync(0xFFFFFFFFu, s2, off);
        s3 += __shfl_xor_sync(0xFFFFFFFFu, s3, off);
    }

    if (lane == 0) {
        g_p[node] = make_float4(s0 + __ldg(b + 0), s1 + __ldg(b + 1), s2, s3);
    }
}

// ---------------------------------------------------------------------------
// Phase 2: 4 edges per thread. int4 index loads (indices are INT32 — JAX
// downcasts int64 randint without x64), float4 table gathers (L2-resident),
// two float4 coalesced output stores.
// ---------------------------------------------------------------------------
__global__ void __launch_bounds__(256)
edge_score_kernel(const int* __restrict__ src,
                  const int* __restrict__ dst,
                  float* __restrict__ out,
                  int n_edges)
{
    const int q = blockIdx.x * blockDim.x + threadIdx.x; // quad index
    const int e = q * 4;
    if (e >= n_edges) return;

    if (e + 3 < n_edges) {
        const int4 s4 = __ldg(((const int4*)src) + q);
        const int4 d4 = __ldg(((const int4*)dst) + q);

        const float4 ps0 = __ldg(&g_p[s4.x]);
        const float4 pd0 = __ldg(&g_p[d4.x]);
        const float4 ps1 = __ldg(&g_p[s4.y]);
        const float4 pd1 = __ldg(&g_p[d4.y]);
        const float4 ps2 = __ldg(&g_p[s4.z]);
        const float4 pd2 = __ldg(&g_p[d4.z]);
        const float4 ps3 = __ldg(&g_p[s4.w]);
        const float4 pd3 = __ldg(&g_p[d4.w]);

        float4 o0, o1;
        o0.x = ps0.x + pd0.z;  o0.y = ps0.y + pd0.w;
        o0.z = ps1.x + pd1.z;  o0.w = ps1.y + pd1.w;
        o1.x = ps2.x + pd2.z;  o1.y = ps2.y + pd2.w;
        o1.z = ps3.x + pd3.z;  o1.w = ps3.y + pd3.w;

        ((float4*)out)[q * 2 + 0] = o0;
        ((float4*)out)[q * 2 + 1] = o1;
    } else {
        for (int k = e; k < n_edges; k++) {
            const int s = __ldg(src + k);
            const int d = __ldg(dst + k);
            const float4 ps = __ldg(&g_p[s]);
            const float4 pd = __ldg(&g_p[d]);
            out[(size_t)k * 2 + 0] = ps.x + pd.z;
            out[(size_t)k * 2 + 1] = ps.y + pd.w;
        }
    }
}

// ---------------------------------------------------------------------------
// Inputs in order: h, src, dst, W, b
// ---------------------------------------------------------------------------
extern "C" void kernel_launch(void* const* d_in, const int* in_sizes, int n_in,
                              void* d_out, int out_size)
{
    const float* h   = (const float*)d_in[0];
    const int*   src = (const int*)d_in[1];
    const int*   dst = (const int*)d_in[2];
    const float* W   = (const float*)d_in[3];
    const float* b   = (const float*)d_in[4];
    float*       out = (float*)d_out;

    const int n_nodes = in_sizes[0] / D_DIM;   // 100000
    const int n_edges = in_sizes[1];           // 1600000

    // Phase 1: 1 warp per node, 8 warps/block
    {
        const int warps_per_block = 8;
        const int blocks = (n_nodes + warps_per_block - 1) / warps_per_block;
        node_proj_kernel<<<blocks, warps_per_block * 32>>>(h, W, b, n_nodes);
    }

    // Phase 2: 4 edges per thread
    {
        const int quads = (n_edges + 3) / 4;
        const int threads = 256;
        const int blocks = (quads + threads - 1) / threads;
        edge_score_kernel<<<blocks, threads>>>(src, dst, out, n_edges);
    }
}

// round 15
// speedup vs baseline: 1.0173x; 1.0173x over previous
#include <cuda_runtime.h>
#include <stdint.h>

#define N_NODES_MAX 100000
#define D_DIM 128

// Per-node projection table: {h·Wu[0]+b0, h·Wu[1]+b1, h·Wv[0], h·Wv[1]}
__device__ float4 g_p[N_NODES_MAX];

// ---------------------------------------------------------------------------
// Phase 1: one warp per node. Each lane loads one float4 of the 128-wide h row
// (32 lanes * 4 = 128), dots against W slices, warp-reduces 4 sums.
// ---------------------------------------------------------------------------
__global__ void __launch_bounds__(256)
node_proj_kernel(const float* __restrict__ h,
                 const float* __restrict__ W,   // [2, 256] row-major
                 const float* __restrict__ b,
                 int n_nodes)
{
    const int warp_in_block = threadIdx.x >> 5;
    const int lane          = threadIdx.x & 31;
    const int node = blockIdx.x * (blockDim.x >> 5) + warp_in_block;
    if (node >= n_nodes) return;

    const float4 hv = __ldg(((const float4*)(h + (size_t)node * D_DIM)) + lane);

    // W row 0 = [Wu0 (128) | Wv0 (128)], row 1 = [Wu1 | Wv1]
    const float4 wu0 = __ldg(((const float4*)(W      )) + lane);
    const float4 wv0 = __ldg(((const float4*)(W + 128)) + lane);
    const float4 wu1 = __ldg(((const float4*)(W + 256)) + lane);
    const float4 wv1 = __ldg(((const float4*)(W + 384)) + lane);

    float s0 = hv.x*wu0.x + hv.y*wu0.y + hv.z*wu0.z + hv.w*wu0.w;
    float s1 = hv.x*wu1.x + hv.y*wu1.y + hv.z*wu1.z + hv.w*wu1.w;
    float s2 = hv.x*wv0.x + hv.y*wv0.y + hv.z*wv0.z + hv.w*wv0.w;
    float s3 = hv.x*wv1.x + hv.y*wv1.y + hv.z*wv1.z + hv.w*wv1.w;

    #pragma unroll
    for (int off = 16; off > 0; off >>= 1) {
        s0 += __shfl_xor_sync(0xFFFFFFFFu, s0, off);
        s1 += __shfl_xor_sync(0xFFFFFFFFu, s1, off);
        s2 += __shfl_xor_sync(0xFFFFFFFFu, s2, off);
        s3 += __shfl_xor_sync(0xFFFFFFFFu, s3, off);
    }

    if (lane == 0) {
        g_p[node] = make_float4(s0 + __ldg(b + 0), s1 + __ldg(b + 1), s2, s3);
    }
}

// ---------------------------------------------------------------------------
// Phase 2: 4 edges per thread. int4 index loads (indices are INT32 — JAX
// downcasts int64 randint without x64), float4 table gathers (L2-resident),
// two float4 coalesced output stores.
// ---------------------------------------------------------------------------
__global__ void __launch_bounds__(256)
edge_score_kernel(const int* __restrict__ src,
                  const int* __restrict__ dst,
                  float* __restrict__ out,
                  int n_edges)
{
    const int q = blockIdx.x * blockDim.x + threadIdx.x; // quad index
    const int e = q * 4;
    if (e >= n_edges) return;

    if (e + 3 < n_edges) {
        const int4 s4 = __ldg(((const int4*)src) + q);
        const int4 d4 = __ldg(((const int4*)dst) + q);

        const float4 ps0 = __ldg(&g_p[s4.x]);
        const float4 pd0 = __ldg(&g_p[d4.x]);
        const float4 ps1 = __ldg(&g_p[s4.y]);
        const float4 pd1 = __ldg(&g_p[d4.y]);
        const float4 ps2 = __ldg(&g_p[s4.z]);
        const float4 pd2 = __ldg(&g_p[d4.z]);
        const float4 ps3 = __ldg(&g_p[s4.w]);
        const float4 pd3 = __ldg(&g_p[d4.w]);

        float4 o0, o1;
        o0.x = ps0.x + pd0.z;  o0.y = ps0.y + pd0.w;
        o0.z = ps1.x + pd1.z;  o0.w = ps1.y + pd1.w;
        o1.x = ps2.x + pd2.z;  o1.y = ps2.y + pd2.w;
        o1.z = ps3.x + pd3.z;  o1.w = ps3.y + pd3.w;

        ((float4*)out)[q * 2 + 0] = o0;
        ((float4*)out)[q * 2 + 1] = o1;
    } else {
        for (int k = e; k < n_edges; k++) {
            const int s = __ldg(src + k);
            const int d = __ldg(dst + k);
            const float4 ps = __ldg(&g_p[s]);
            const float4 pd = __ldg(&g_p[d]);
            out[(size_t)k * 2 + 0] = ps.x + pd.z;
            out[(size_t)k * 2 + 1] = ps.y + pd.w;
        }
    }
}

// ---------------------------------------------------------------------------
// Inputs in order: h, src, dst, W, b
// ---------------------------------------------------------------------------
extern "C" void kernel_launch(void* const* d_in, const int* in_sizes, int n_in,
                              void* d_out, int out_size)
{
    const float* h   = (const float*)d_in[0];
    const int*   src = (const int*)d_in[1];
    const int*   dst = (const int*)d_in[2];
    const float* W   = (const float*)d_in[3];
    const float* b   = (const float*)d_in[4];
    float*       out = (float*)d_out;

    const int n_nodes = in_sizes[0] / D_DIM;   // 100000
    const int n_edges = in_sizes[1];           // 1600000

    // Phase 1: 1 warp per node, 8 warps/block
    {
        const int warps_per_block = 8;
        const int blocks = (n_nodes + warps_per_block - 1) / warps_per_block;
        node_proj_kernel<<<blocks, warps_per_block * 32>>>(h, W, b, n_nodes);
    }

    // Phase 2: 4 edges per thread
    {
        const int quads = (n_edges + 3) / 4;
        const int threads = 256;
        const int blocks = (quads + threads - 1) / threads;
        edge_score_kernel<<<blocks, threads>>>(src, dst, out, n_edges);
    }
}

// round 16
// speedup vs baseline: 1.0182x; 1.0009x over previous
#include <cuda_runtime.h>
#include <stdint.h>

#define N_NODES_MAX 100000
#define D_DIM 128

// Per-node projection table: {h·Wu[0]+b0, h·Wu[1]+b1, h·Wv[0], h·Wv[1]}
__device__ float4 g_p[N_NODES_MAX];

// ---------------------------------------------------------------------------
// Phase 1: one warp per node. Each lane loads one float4 of the 128-wide h row
// (32 lanes * 4 = 128), dots against W slices, warp-reduces 4 sums.
// ---------------------------------------------------------------------------
__global__ void __launch_bounds__(256)
node_proj_kernel(const float* __restrict__ h,
                 const float* __restrict__ W,   // [2, 256] row-major
                 const float* __restrict__ b,
                 int n_nodes)
{
    const int warp_in_block = threadIdx.x >> 5;
    const int lane          = threadIdx.x & 31;
    const int node = blockIdx.x * (blockDim.x >> 5) + warp_in_block;
    if (node >= n_nodes) return;

    const float4 hv = __ldg(((const float4*)(h + (size_t)node * D_DIM)) + lane);

    // W row 0 = [Wu0 (128) | Wv0 (128)], row 1 = [Wu1 | Wv1]
    const float4 wu0 = __ldg(((const float4*)(W      )) + lane);
    const float4 wv0 = __ldg(((const float4*)(W + 128)) + lane);
    const float4 wu1 = __ldg(((const float4*)(W + 256)) + lane);
    const float4 wv1 = __ldg(((const float4*)(W + 384)) + lane);

    float s0 = hv.x*wu0.x + hv.y*wu0.y + hv.z*wu0.z + hv.w*wu0.w;
    float s1 = hv.x*wu1.x + hv.y*wu1.y + hv.z*wu1.z + hv.w*wu1.w;
    float s2 = hv.x*wv0.x + hv.y*wv0.y + hv.z*wv0.z + hv.w*wv0.w;
    float s3 = hv.x*wv1.x + hv.y*wv1.y + hv.z*wv1.z + hv.w*wv1.w;

    #pragma unroll
    for (int off = 16; off > 0; off >>= 1) {
        s0 += __shfl_xor_sync(0xFFFFFFFFu, s0, off);
        s1 += __shfl_xor_sync(0xFFFFFFFFu, s1, off);
        s2 += __shfl_xor_sync(0xFFFFFFFFu, s2, off);
        s3 += __shfl_xor_sync(0xFFFFFFFFu, s3, off);
    }

    if (lane == 0) {
        g_p[node] = make_float4(s0 + __ldg(b + 0), s1 + __ldg(b + 1), s2, s3);
    }
}

// ---------------------------------------------------------------------------
// Phase 2: 4 edges per thread. int4 index loads (indices are INT32 — JAX
// downcasts int64 randint without x64), float4 table gathers (L2-resident),
// two float4 coalesced output stores.
// ---------------------------------------------------------------------------
__global__ void __launch_bounds__(256)
edge_score_kernel(const int* __restrict__ src,
                  const int* __restrict__ dst,
                  float* __restrict__ out,
                  int n_edges)
{
    const int q = blockIdx.x * blockDim.x + threadIdx.x; // quad index
    const int e = q * 4;
    if (e >= n_edges) return;

    if (e + 3 < n_edges) {
        const int4 s4 = __ldg(((const int4*)src) + q);
        const int4 d4 = __ldg(((const int4*)dst) + q);

        const float4 ps0 = __ldg(&g_p[s4.x]);
        const float4 pd0 = __ldg(&g_p[d4.x]);
        const float4 ps1 = __ldg(&g_p[s4.y]);
        const float4 pd1 = __ldg(&g_p[d4.y]);
        const float4 ps2 = __ldg(&g_p[s4.z]);
        const float4 pd2 = __ldg(&g_p[d4.z]);
        const float4 ps3 = __ldg(&g_p[s4.w]);
        const float4 pd3 = __ldg(&g_p[d4.w]);

        float4 o0, o1;
        o0.x = ps0.x + pd0.z;  o0.y = ps0.y + pd0.w;
        o0.z = ps1.x + pd1.z;  o0.w = ps1.y + pd1.w;
        o1.x = ps2.x + pd2.z;  o1.y = ps2.y + pd2.w;
        o1.z = ps3.x + pd3.z;  o1.w = ps3.y + pd3.w;

        ((float4*)out)[q * 2 + 0] = o0;
        ((float4*)out)[q * 2 + 1] = o1;
    } else {
        for (int k = e; k < n_edges; k++) {
            const int s = __ldg(src + k);
            const int d = __ldg(dst + k);
            const float4 ps = __ldg(&g_p[s]);
            const float4 pd = __ldg(&g_p[d]);
            out[(size_t)k * 2 + 0] = ps.x + pd.z;
            out[(size_t)k * 2 + 1] = ps.y + pd.w;
        }
    }
}

// ---------------------------------------------------------------------------
// Inputs in order: h, src, dst, W, b
// ---------------------------------------------------------------------------
extern "C" void kernel_launch(void* const* d_in, const int* in_sizes, int n_in,
                              void* d_out, int out_size)
{
    const float* h   = (const float*)d_in[0];
    const int*   src = (const int*)d_in[1];
    const int*   dst = (const int*)d_in[2];
    const float* W   = (const float*)d_in[3];
    const float* b   = (const float*)d_in[4];
    float*       out = (float*)d_out;

    const int n_nodes = in_sizes[0] / D_DIM;   // 100000
    const int n_edges = in_sizes[1];           // 1600000

    // Phase 1: 1 warp per node, 8 warps/block
    {
        const int warps_per_block = 8;
        const int blocks = (n_nodes + warps_per_block - 1) / warps_per_block;
        node_proj_kernel<<<blocks, warps_per_block * 32>>>(h, W, b, n_nodes);
    }

    // Phase 2: 4 edges per thread
    {
        const int quads = (n_edges + 3) / 4;
        const int threads = 256;
        const int blocks = (quads + threads - 1) / threads;
        edge_score_kernel<<<blocks, threads>>>(src, dst, out, n_edges);
    }
}